// round 16
// baseline (speedup 1.0000x reference)
#include <cuda_runtime.h>
#include <cuda_fp16.h>
#include <math.h>
#include <stdint.h>

#define Bb 4
#define Tt 4096
#define Cc 1024
#define Hh 64
#define BM 64       // queries per attention CTA
#define KT 32       // keys per inner tile
#define NSPLIT 8
#define SCALE 0.03125f   // C^-0.5 = 1/32

// ---- scratch (no cudaMalloc allowed) ----
// q/k/v stored as packed half2 (pairs along h): Hh/2 = 32 words per row
__device__ uint32_t g_qh[Bb*Tt*Hh/2];
__device__ uint32_t g_kh[Bb*Tt*Hh/2];
__device__ uint32_t g_vh[Bb*Tt*Hh/2];
__device__ float g_pm[Bb*Tt*NSPLIT];
__device__ float g_pl[Bb*Tt*NSPLIT];
__device__ float g_pacc[(size_t)Bb*Tt*NSPLIT*Hh];

__device__ __forceinline__ uint32_t pack2(float a, float b) {
    __half2 h = __floats2half2_rn(a, b);   // low = a, high = b
    return *reinterpret_cast<uint32_t*>(&h);
}

// mma m16n8k16 fp16 inputs, f32 accumulate
__device__ __forceinline__ void mma_f16(float* d, const uint32_t* a, uint32_t b0, uint32_t b1) {
    asm volatile(
        "mma.sync.aligned.m16n8k16.row.col.f32.f16.f16.f32 "
        "{%0,%1,%2,%3}, {%4,%5,%6,%7}, {%8,%9}, {%0,%1,%2,%3};"
        : "+f"(d[0]), "+f"(d[1]), "+f"(d[2]), "+f"(d[3])
        : "r"(a[0]), "r"(a[1]), "r"(a[2]), "r"(a[3]), "r"(b0), "r"(b1));
}

// ============================================================
// Kernel 1: FUSED QKV projection (R14 exact: double-buffered).
// ============================================================
#define PA_S 20      // words per A row (16 h2 + 4 pad)
#define PB_S 200     // words per Bs k2-row (192 n + 8 pad)

__global__ __launch_bounds__(256) void proj_fused_kernel(
    const float* __restrict__ x,
    const float* __restrict__ Wq,
    const float* __restrict__ Wk,
    const float* __restrict__ Wv)
{
    __shared__ uint32_t As2[2][128 * PA_S];
    __shared__ uint32_t Bs2[2][16 * PB_S];

    const int row0 = blockIdx.x * 128;
    const int tid = threadIdx.x;
    const int wid = tid >> 5, lid = tid & 31;
    const int wm = wid >> 2;
    const int wn = wid & 3;
    const int m0 = wm * 64;
    const int n0 = wn * 6;
    const int fr = lid >> 2;
    const int fc = lid & 3;

    const int a_m[4] = { (tid + 0) >> 3, (tid + 256) >> 3, (tid + 512) >> 3, (tid + 768) >> 3 };
    const int a_c4 = tid & 7;
    const int b_k2 = tid >> 4, b_n4 = tid & 15;

    float acc[4][6][4];
#pragma unroll
    for (int mt = 0; mt < 4; ++mt)
#pragma unroll
        for (int j = 0; j < 6; ++j)
#pragma unroll
            for (int u = 0; u < 4; ++u) acc[mt][j][u] = 0.f;

    {
#pragma unroll
        for (int r = 0; r < 4; ++r) {
            float4 a = *reinterpret_cast<const float4*>(x + (size_t)(row0 + a_m[r]) * Cc + a_c4 * 4);
            As2[0][a_m[r] * PA_S + a_c4 * 2    ] = pack2(a.x, a.y);
            As2[0][a_m[r] * PA_S + a_c4 * 2 + 1] = pack2(a.z, a.w);
        }
#pragma unroll
        for (int mat = 0; mat < 3; ++mat) {
            const float* W = (mat == 0) ? Wq : (mat == 1) ? Wk : Wv;
            float4 w0 = *reinterpret_cast<const float4*>(W + (size_t)(2 * b_k2    ) * Hh + b_n4 * 4);
            float4 w1 = *reinterpret_cast<const float4*>(W + (size_t)(2 * b_k2 + 1) * Hh + b_n4 * 4);
            uint32_t* d = &Bs2[0][b_k2 * PB_S + mat * 64 + b_n4 * 4];
            d[0] = pack2(w0.x, w1.x);
            d[1] = pack2(w0.y, w1.y);
            d[2] = pack2(w0.z, w1.z);
            d[3] = pack2(w0.w, w1.w);
        }
    }
    __syncthreads();

    int buf = 0;
    for (int kc = 0; kc < Cc / 32; ++kc) {
        const int nb = buf ^ 1;
        const bool have_next = (kc + 1 < Cc / 32);

        float4 an[4], w0n[3], w1n[3];
        if (have_next) {
            const int k0n = (kc + 1) * 32;
#pragma unroll
            for (int r = 0; r < 4; ++r)
                an[r] = *reinterpret_cast<const float4*>(x + (size_t)(row0 + a_m[r]) * Cc + k0n + a_c4 * 4);
#pragma unroll
            for (int mat = 0; mat < 3; ++mat) {
                const float* W = (mat == 0) ? Wq : (mat == 1) ? Wk : Wv;
                w0n[mat] = *reinterpret_cast<const float4*>(W + (size_t)(k0n + 2 * b_k2    ) * Hh + b_n4 * 4);
                w1n[mat] = *reinterpret_cast<const float4*>(W + (size_t)(k0n + 2 * b_k2 + 1) * Hh + b_n4 * 4);
            }
        }

#pragma unroll
        for (int w = 0; w < 2; ++w) {
            uint32_t af[4][4];
#pragma unroll
            for (int mt = 0; mt < 4; ++mt) {
                const int rb = (m0 + mt * 16 + fr) * PA_S;
                const int rb8 = rb + 8 * PA_S;
                af[mt][0] = As2[buf][rb  + w * 8 + fc    ];
                af[mt][1] = As2[buf][rb8 + w * 8 + fc    ];
                af[mt][2] = As2[buf][rb  + w * 8 + fc + 4];
                af[mt][3] = As2[buf][rb8 + w * 8 + fc + 4];
            }
            uint32_t bf[6][2];
#pragma unroll
            for (int j = 0; j < 6; ++j) {
                int col = (n0 + j) * 8 + fr;
                bf[j][0] = Bs2[buf][(w * 8 + fc    ) * PB_S + col];
                bf[j][1] = Bs2[buf][(w * 8 + fc + 4) * PB_S + col];
            }
#pragma unroll
            for (int mt = 0; mt < 4; ++mt)
#pragma unroll
                for (int j = 0; j < 6; ++j)
                    mma_f16(acc[mt][j], af[mt], bf[j][0], bf[j][1]);
        }

        if (have_next) {
#pragma unroll
            for (int r = 0; r < 4; ++r) {
                As2[nb][a_m[r] * PA_S + a_c4 * 2    ] = pack2(an[r].x, an[r].y);
                As2[nb][a_m[r] * PA_S + a_c4 * 2 + 1] = pack2(an[r].z, an[r].w);
            }
#pragma unroll
            for (int mat = 0; mat < 3; ++mat) {
                uint32_t* d = &Bs2[nb][b_k2 * PB_S + mat * 64 + b_n4 * 4];
                d[0] = pack2(w0n[mat].x, w1n[mat].x);
                d[1] = pack2(w0n[mat].y, w1n[mat].y);
                d[2] = pack2(w0n[mat].z, w1n[mat].z);
                d[3] = pack2(w0n[mat].w, w1n[mat].w);
            }
        }
        __syncthreads();
        buf = nb;
    }

#pragma unroll
    for (int mt = 0; mt < 4; ++mt) {
#pragma unroll
        for (int j = 0; j < 6; ++j) {
            int nt_g = n0 + j;
            int mat = nt_g >> 3;
            int jj = nt_g & 7;
            uint32_t* outp = (mat == 0) ? g_qh : (mat == 1) ? g_kh : g_vh;
            uint32_t* obase = outp + (size_t)(row0 + m0 + mt * 16) * (Hh / 2);
            int colw = jj * 4 + fc;
            obase[(size_t)fr * (Hh / 2) + colw]       = pack2(acc[mt][j][0], acc[mt][j][1]);
            obase[(size_t)(fr + 8) * (Hh / 2) + colw] = pack2(acc[mt][j][2], acc[mt][j][3]);
        }
    }
}

// ============================================================
// Kernel 2: flash attention, BM=64, 128 threads (4 warps),
// double-buffered K/V, unnormalized exp, fp16 m16n8k16.
// 33KB smem + ~halved regs/CTA -> 2-3 CTAs/SM.
// ============================================================
#define QS_S 36      // words per Q row (32 h2 + 4 pad)
#define PS2_S 20     // words per P row (16 key2 + 4 pad)
#define KS2_S 36     // words per K row (32 h2 + 4 pad)
#define VS2_S 20     // words per V h-row (16 key2 + 4 pad)

__global__ __launch_bounds__(128, 3) void attn_mma_kernel()
{
    __shared__ uint32_t Qs2[BM * QS_S];          // 9216 B
    __shared__ uint32_t Ps2[BM * PS2_S];         // 5120 B
    __shared__ uint32_t Ks2[2][KT * KS2_S];      // 9216 B
    __shared__ uint32_t Vs2[2][Hh * VS2_S];      // 10240 B  (total ~33 KB)
    __half* PsH = reinterpret_cast<__half*>(Ps2);

    const int qt = (Tt / BM - 1) - blockIdx.x;   // big tiles first
    const int sp = blockIdx.y;
    const int b  = blockIdx.z;
    const int q0 = qt * BM;
    const int tid = threadIdx.x, wid = tid >> 5, lid = tid & 31;
    const int fr = lid >> 2, fc = lid & 3;
    const int m0 = wid * 16;

    const int n_kt = (qt + 1) * (BM / KT);
    const int per = (n_kt + NSPLIT - 1) / NSPLIT;
    const int kt0 = sp * per;
    const int kt1 = min(kt0 + per, n_kt);

    if (kt0 >= kt1) {   // empty split: zero partials
        int q = tid >> 1, half = tid & 1;
        size_t pidx = ((size_t)b * Tt + q0 + q) * NSPLIT + sp;
        if (half == 0) { g_pm[pidx] = -1e30f; g_pl[pidx] = 0.f; }
        float4 z = make_float4(0.f, 0.f, 0.f, 0.f);
        float4* pa = reinterpret_cast<float4*>(g_pacc + pidx * Hh) + half * 8;
#pragma unroll
        for (int i2 = 0; i2 < 8; ++i2) pa[i2] = z;
        return;
    }

    // ---- stage Q: raw uint4 copy (64 rows x 8 groups = 512 / 128 thr) ----
#pragma unroll
    for (int r = 0; r < 4; ++r) {
        int f = tid + r * 128;
        int q = f >> 3, g = f & 7;
        const uint4 v = *reinterpret_cast<const uint4*>(g_qh + ((size_t)b * Tt + q0 + q) * 32 + g * 4);
        *reinterpret_cast<uint4*>(&Qs2[q * QS_S + g * 4]) = v;
    }

    // ---- prologue: load first K/V tile into buffer 0 (2 items/thread) ----
    {
        __half* VsH0 = reinterpret_cast<__half*>(Vs2[0]);
#pragma unroll
        for (int r = 0; r < 2; ++r) {
            int f = tid + r * 128;
            int key = f >> 3, g = f & 7;
            size_t gbase = ((size_t)b * Tt + kt0 * KT + key) * 32 + g * 4;
            const uint4 kv = *reinterpret_cast<const uint4*>(g_kh + gbase);
            *reinterpret_cast<uint4*>(&Ks2[0][key * KS2_S + g * 4]) = kv;
            const uint4 vv = *reinterpret_cast<const uint4*>(g_vh + gbase);
            uint32_t vw[4] = {vv.x, vv.y, vv.z, vv.w};
#pragma unroll
            for (int jw = 0; jw < 4; ++jw) {
                __half2 h2 = *reinterpret_cast<__half2*>(&vw[jw]);
                int h0 = g * 8 + jw * 2;
                VsH0[(h0    ) * (VS2_S * 2) + key] = __low2half(h2);
                VsH0[(h0 + 1) * (VS2_S * 2) + key] = __high2half(h2);
            }
        }
    }
    __syncthreads();

    // hoist Q fragments
    uint32_t qf[4][2][2];
#pragma unroll
    for (int w = 0; w < 4; ++w)
#pragma unroll
        for (int nt = 0; nt < 2; ++nt) {
            int qcol = m0 + nt * 8 + fr;
            qf[w][nt][0] = Qs2[qcol * QS_S + w * 8 + fc    ];
            qf[w][nt][1] = Qs2[qcol * QS_S + w * 8 + fc + 4];
        }

    float o[8][4];
#pragma unroll
    for (int nt = 0; nt < 8; ++nt)
#pragma unroll
        for (int u = 0; u < 4; ++u) o[nt][u] = 0.f;
    float l_acc[2][2];
    l_acc[0][0] = l_acc[0][1] = l_acc[1][0] = l_acc[1][1] = 0.f;

    int buf = 0;
    for (int kt = kt0; kt < kt1; ++kt) {
        const int jb = kt * KT;
        const int nb = buf ^ 1;
        const bool have_next = (kt + 1 < kt1);

        // ---- issue next tile's LDGs now ----
        uint4 kv_n[2], vv_n[2];
        if (have_next) {
#pragma unroll
            for (int r = 0; r < 2; ++r) {
                int f = tid + r * 128;
                int key = f >> 3, g = f & 7;
                size_t gbase = ((size_t)b * Tt + jb + KT + key) * 32 + g * 4;
                kv_n[r] = *reinterpret_cast<const uint4*>(g_kh + gbase);
                vv_n[r] = *reinterpret_cast<const uint4*>(g_vh + gbase);
            }
        }

        // ---- S^T = K @ Q^T : 16 MMAs on current buffer ----
        float sacc[2][2][4];
#pragma unroll
        for (int mt = 0; mt < 2; ++mt)
#pragma unroll
            for (int nt = 0; nt < 2; ++nt)
#pragma unroll
                for (int u = 0; u < 4; ++u) sacc[mt][nt][u] = 0.f;
#pragma unroll
        for (int w = 0; w < 4; ++w) {
            uint32_t ak[2][4];
#pragma unroll
            for (int mt = 0; mt < 2; ++mt) {
                const int rb  = (16 * mt + fr) * KS2_S;
                const int rb8 = rb + 8 * KS2_S;
                ak[mt][0] = Ks2[buf][rb  + w * 8 + fc    ];
                ak[mt][1] = Ks2[buf][rb8 + w * 8 + fc    ];
                ak[mt][2] = Ks2[buf][rb  + w * 8 + fc + 4];
                ak[mt][3] = Ks2[buf][rb8 + w * 8 + fc + 4];
            }
#pragma unroll
            for (int mt = 0; mt < 2; ++mt)
#pragma unroll
                for (int nt = 0; nt < 2; ++nt)
                    mma_f16(sacc[mt][nt], ak[mt], qf[w][nt][0], qf[w][nt][1]);
        }

        // ---- unnormalized exp ----
#pragma unroll
        for (int nt = 0; nt < 2; ++nt)
#pragma unroll
        for (int cp = 0; cp < 2; ++cp) {
            const int qloc = m0 + 8 * nt + 2 * fc + cp;
            const int qg = q0 + qloc;
            float ts = 0.f;
#pragma unroll
            for (int mt = 0; mt < 2; ++mt)
#pragma unroll
                for (int s2 = 0; s2 < 2; ++s2) {
                    int keyg = jb + 16 * mt + 8 * s2 + fr;
                    float p = (keyg <= qg) ? __expf(sacc[mt][nt][s2 * 2 + cp] * SCALE) : 0.f;
                    ts += p;
                    PsH[qloc * (PS2_S * 2) + 16 * mt + 8 * s2 + fr] = __float2half_rn(p);
                }
            l_acc[nt][cp] += ts;
        }
        __syncwarp();

        // ---- O += P @ V : 16 MMAs on current buffer ----
#pragma unroll
        for (int w = 0; w < 2; ++w) {
            uint32_t ap[4];
            const int rb  = (m0 + fr) * PS2_S;
            const int rb8 = rb + 8 * PS2_S;
            ap[0] = Ps2[rb  + w * 8 + fc    ];
            ap[1] = Ps2[rb8 + w * 8 + fc    ];
            ap[2] = Ps2[rb  + w * 8 + fc + 4];
            ap[3] = Ps2[rb8 + w * 8 + fc + 4];
#pragma unroll
            for (int nt = 0; nt < 8; ++nt) {
                int col = nt * 8 + fr;
                uint32_t b0 = Vs2[buf][col * VS2_S + w * 8 + fc    ];
                uint32_t b1 = Vs2[buf][col * VS2_S + w * 8 + fc + 4];
                mma_f16(o[nt], ap, b0, b1);
            }
        }

        // ---- store prefetched next tile into alternate buffer ----
        if (have_next) {
            __half* VsHn = reinterpret_cast<__half*>(Vs2[nb]);
#pragma unroll
            for (int r = 0; r < 2; ++r) {
                int f = tid + r * 128;
                int key = f >> 3, g = f & 7;
                *reinterpret_cast<uint4*>(&Ks2[nb][key * KS2_S + g * 4]) = kv_n[r];
                uint32_t vw[4] = {vv_n[r].x, vv_n[r].y, vv_n[r].z, vv_n[r].w};
#pragma unroll
                for (int jw = 0; jw < 4; ++jw) {
                    __half2 h2 = *reinterpret_cast<__half2*>(&vw[jw]);
                    int h0 = g * 8 + jw * 2;
                    VsHn[(h0    ) * (VS2_S * 2) + key] = __low2half(h2);
                    VsHn[(h0 + 1) * (VS2_S * 2) + key] = __high2half(h2);
                }
            }
        }
        __syncthreads();
        buf = nb;
    }

    // ---- finalize l and store partials ----
#pragma unroll
    for (int nt = 0; nt < 2; ++nt)
#pragma unroll
        for (int cp = 0; cp < 2; ++cp) {
            float tl = l_acc[nt][cp];
            tl += __shfl_xor_sync(0xffffffffu, tl, 4);
            tl += __shfl_xor_sync(0xffffffffu, tl, 8);
            tl += __shfl_xor_sync(0xffffffffu, tl, 16);
            if (fr == 0) {
                int qloc = m0 + 8 * nt + 2 * fc + cp;
                size_t pidx = ((size_t)b * Tt + q0 + qloc) * NSPLIT + sp;
                g_pm[pidx] = 0.f;
                g_pl[pidx] = tl;
            }
        }
    {
        size_t p_lo = ((size_t)b * Tt + q0 + m0 + fr    ) * NSPLIT + sp;
        size_t p_hi = ((size_t)b * Tt + q0 + m0 + fr + 8) * NSPLIT + sp;
        float* alo = g_pacc + p_lo * Hh;
        float* ahi = g_pacc + p_hi * Hh;
#pragma unroll
        for (int nt = 0; nt < 8; ++nt) {
            int col = nt * 8 + 2 * fc;
            *reinterpret_cast<float2*>(alo + col) = make_float2(o[nt][0], o[nt][1]);
            *reinterpret_cast<float2*>(ahi + col) = make_float2(o[nt][2], o[nt][3]);
        }
    }
}

// ============================================================
// Kernel 3: merge splits (unchanged).
// ============================================================
__global__ __launch_bounds__(128) void attn_reduce_kernel(float* __restrict__ out)
{
    const int tid = threadIdx.x;
    const size_t qq = (size_t)blockIdx.x * 2 + (tid >> 6);
    const int h = tid & 63;

    float m_tot = -1e30f;
#pragma unroll
    for (int s = 0; s < NSPLIT; ++s)
        m_tot = fmaxf(m_tot, g_pm[qq * NSPLIT + s]);

    float num = 0.f, den = 0.f;
#pragma unroll
    for (int s = 0; s < NSPLIT; ++s) {
        float w = __expf(g_pm[qq * NSPLIT + s] - m_tot);
        den += w * g_pl[qq * NSPLIT + s];
        num += w * g_pacc[(qq * NSPLIT + s) * Hh + h];
    }
    out[qq * Hh + h] = num / den;
}

// ============================================================
extern "C" void kernel_launch(void* const* d_in, const int* in_sizes, int n_in,
                              void* d_out, int out_size)
{
    const float* x  = (const float*)d_in[0];
    const float* Wq = (const float*)d_in[1];
    const float* Wk = (const float*)d_in[2];
    const float* Wv = (const float*)d_in[3];
    float* out = (float*)d_out;

    proj_fused_kernel<<<Bb * Tt / 128, 256>>>(x, Wq, Wk, Wv);

    dim3 agrid(Tt / BM, NSPLIT, Bb);
    attn_mma_kernel<<<agrid, 128>>>();

    attn_reduce_kernel<<<Bb * Tt / 2, 128>>>(out);
}